// round 5
// baseline (speedup 1.0000x reference)
#include <cuda_runtime.h>
#include <math_constants.h>

#define T_TOKENS 16384
#define N_EXP    256
#define KDIM     7168
#define TOPKN    8
#define NGROUPS  8
#define TOPG     4
#define ROUTE_SCALE 2.5f

// Scratch: sigmoid scores [T, 256] (16 MB) — __device__ global per no-alloc rule.
__device__ float g_scores[(size_t)T_TOKENS * N_EXP];

// ---------------------------------------------------------------------------
// Kernel 1: scores = sigmoid(X @ W^T).  M=16384, N=256, K=7168, fp32.
// Accumulation structure: ascending-k FMA within each BK=32 chunk (register
// accumulator), plain fp32 add of chunk sums in ascending chunk order —
// mirrors the chunked-sequential structure of Eigen/Triton/cutlass fp32
// GEMMs (the plausible reference family). Total noise σ ≈ 3e-7 absolute.
// ---------------------------------------------------------------------------
#define BM 128
#define BN 64
#define BK 32
#define TM 8
#define TN 4

__global__ __launch_bounds__(256) void gemm_sigmoid_kernel(
    const float* __restrict__ X, const float* __restrict__ W)
{
    __shared__ float As[BK][BM];
    __shared__ float Bs[BK][BN];

    const int bm = blockIdx.y * BM;
    const int bn = blockIdx.x * BN;
    const int tid = threadIdx.x;
    const int tx = tid & 15;   // N direction (16 threads * TN=4 -> 64)
    const int ty = tid >> 4;   // M direction (16 threads * TM=8 -> 128)

    float sum[TM][TN];
    #pragma unroll
    for (int i = 0; i < TM; i++)
        #pragma unroll
        for (int j = 0; j < TN; j++) sum[i][j] = 0.0f;

    for (int k0 = 0; k0 < KDIM; k0 += BK) {
        // Load A tile: 128 rows x 32 k = 1024 float4, 4 per thread.
        #pragma unroll
        for (int i = 0; i < 4; i++) {
            int f   = tid + i * 256;
            int row = f >> 3;            // 8 float4 per row
            int kc  = (f & 7) << 2;
            float4 v = *(const float4*)(X + (size_t)(bm + row) * KDIM + k0 + kc);
            As[kc + 0][row] = v.x;
            As[kc + 1][row] = v.y;
            As[kc + 2][row] = v.z;
            As[kc + 3][row] = v.w;
        }
        // Load B tile: 64 rows x 32 k = 512 float4, 2 per thread.
        #pragma unroll
        for (int i = 0; i < 2; i++) {
            int f   = tid + i * 256;
            int row = f >> 3;
            int kc  = (f & 7) << 2;
            float4 v = *(const float4*)(W + (size_t)(bn + row) * KDIM + k0 + kc);
            Bs[kc + 0][row] = v.x;
            Bs[kc + 1][row] = v.y;
            Bs[kc + 2][row] = v.z;
            Bs[kc + 3][row] = v.w;
        }
        __syncthreads();

        // Chunk-local accumulators (ascending k, exact FMA ordering).
        float cacc[TM][TN];
        #pragma unroll
        for (int i = 0; i < TM; i++)
            #pragma unroll
            for (int j = 0; j < TN; j++) cacc[i][j] = 0.0f;

        #pragma unroll
        for (int k = 0; k < BK; k++) {
            float a[TM], b[TN];
            #pragma unroll
            for (int i = 0; i < TM; i++) a[i] = As[k][ty * TM + i];
            #pragma unroll
            for (int j = 0; j < TN; j++) b[j] = Bs[k][tx * TN + j];
            #pragma unroll
            for (int i = 0; i < TM; i++)
                #pragma unroll
                for (int j = 0; j < TN; j++)
                    cacc[i][j] = __fmaf_rn(a[i], b[j], cacc[i][j]);
        }

        // Plain fp32 merge of the chunk sum, ascending chunk order.
        #pragma unroll
        for (int i = 0; i < TM; i++)
            #pragma unroll
            for (int j = 0; j < TN; j++)
                sum[i][j] = __fadd_rn(sum[i][j], cacc[i][j]);
        __syncthreads();
    }

    #pragma unroll
    for (int i = 0; i < TM; i++) {
        int m = bm + ty * TM + i;
        #pragma unroll
        for (int j = 0; j < TN; j++) {
            int n = bn + tx * TN + j;
            // fp64 sigmoid: correctly-rounded-to-fp32 to ~1 ulp, immune to
            // fast-math expf substitution. Cost negligible vs GEMM.
            double xd = (double)sum[i][j];
            float s = (float)(1.0 / (1.0 + exp(-xd)));
            g_scores[(size_t)m * N_EXP + n] = s;
        }
    }
}

// ---------------------------------------------------------------------------
// Kernel 2: routing. One warp per token. Lane l holds expert g*32+l per group.
// ---------------------------------------------------------------------------
__global__ __launch_bounds__(128) void route_kernel(
    const float* __restrict__ bias, float* __restrict__ out)
{
    __shared__ float sm_orig[4][N_EXP];

    const int warp = threadIdx.x >> 5;
    const int lane = threadIdx.x & 31;
    const int t = blockIdx.x * 4 + warp;

    const float* sc = g_scores + (size_t)t * N_EXP;

    float sb[NGROUPS];
    #pragma unroll
    for (int g = 0; g < NGROUPS; g++) {
        int e = g * 32 + lane;
        float o = sc[e];
        sm_orig[warp][e] = o;
        sb[g] = __fadd_rn(o, bias[e]);
    }
    __syncwarp();

    // Group score = sum of top-2 biased scores per group (32 lanes = 1 group).
    float gs[NGROUPS];
    #pragma unroll
    for (int g = 0; g < NGROUPS; g++) {
        float m1 = sb[g], m2 = -CUDART_INF_F;
        #pragma unroll
        for (int off = 16; off; off >>= 1) {
            float o1 = __shfl_xor_sync(0xffffffffu, m1, off);
            float o2 = __shfl_xor_sync(0xffffffffu, m2, off);
            float hi = fmaxf(m1, o1);
            float lo = fminf(m1, o1);
            m2 = fmaxf(lo, fmaxf(m2, o2));
            m1 = hi;
        }
        gs[g] = __fadd_rn(m1, m2);  // top1 + top2, reference order
    }

    // Top-4 groups (replicated on every lane; strict > => lower index wins tie).
    unsigned gmask = 0;
    #pragma unroll
    for (int it = 0; it < TOPG; it++) {
        float best = -CUDART_INF_F;
        int bi = 0;
        #pragma unroll
        for (int g = 0; g < NGROUPS; g++)
            if (!((gmask >> g) & 1u) && gs[g] > best) { best = gs[g]; bi = g; }
        gmask |= 1u << bi;
    }
    #pragma unroll
    for (int g = 0; g < NGROUPS; g++)
        if (!((gmask >> g) & 1u)) sb[g] = -CUDART_INF_F;

    // Top-8 experts over masked biased scores; descending, lower index on ties.
    int   idxv[TOPKN];
    float wsel[TOPKN];
    float wsum = 0.0f;
    #pragma unroll
    for (int it = 0; it < TOPKN; it++) {
        float bv = -CUDART_INF_F;
        int bg = 0;
        #pragma unroll
        for (int g = 0; g < NGROUPS; g++)
            if (sb[g] > bv) { bv = sb[g]; bg = g; }
        int bidx = bg * 32 + lane;
        if (bv == -CUDART_INF_F) bidx = (1 << 30);

        #pragma unroll
        for (int off = 16; off; off >>= 1) {
            float ov = __shfl_xor_sync(0xffffffffu, bv, off);
            int   oi = __shfl_xor_sync(0xffffffffu, bidx, off);
            if (ov > bv || (ov == bv && oi < bidx)) { bv = ov; bidx = oi; }
        }
        // Owner lane retires the winner (unrolled to keep sb[] in registers).
        int cg = bidx >> 5;
        if ((bidx & 31) == lane) {
            #pragma unroll
            for (int g = 0; g < NGROUPS; g++)
                if (g == cg) sb[g] = -CUDART_INF_F;
        }
        float ow = sm_orig[warp][bidx];  // exact original sigmoid score
        idxv[it] = bidx;
        wsel[it] = ow;
        wsum = __fadd_rn(wsum, ow);      // reference sum order (desc. selection)
    }

    if (lane == 0) {
        float* out_w = out + (size_t)t * TOPKN;
        float* out_i = out + (size_t)T_TOKENS * TOPKN + (size_t)t * TOPKN;
        #pragma unroll
        for (int it = 0; it < TOPKN; it++) {
            out_w[it] = __fmul_rn(__fdiv_rn(wsel[it], wsum), ROUTE_SCALE);
            out_i[it] = (float)idxv[it];
        }
    }
}

// ---------------------------------------------------------------------------
extern "C" void kernel_launch(void* const* d_in, const int* in_sizes, int n_in,
                              void* d_out, int out_size)
{
    const float* x    = (const float*)d_in[0];  // [16384, 7168]
    const float* w    = (const float*)d_in[1];  // [256, 7168]
    const float* bias = (const float*)d_in[2];  // [256]
    float* out = (float*)d_out;                 // [16384*8 weights | 16384*8 indices]

    dim3 ggrid(N_EXP / BN, T_TOKENS / BM);      // (4, 128)
    gemm_sigmoid_kernel<<<ggrid, 256>>>(x, w);

    route_kernel<<<T_TOKENS / 4, 128>>>(bias, out);
}